// round 15
// baseline (speedup 1.0000x reference)
#include <cuda_runtime.h>

// ---------------- static scratch (no dynamic allocation allowed) ------------
#define MAXN 50016
#define MAXE 800000

__device__ float g_H1[MAXN * 64];   // layer-1 features x@W1
__device__ float g_as1[MAXN * 4];   // alpha_src layer1 per head
__device__ float g_ad1[MAXN * 4];   // alpha_dst layer1 per head
__device__ float g_X2[MAXN * 64];   // elu(gat1 output) = input to layer2
__device__ float g_H2[MAXN * 32];   // layer-2 features X2@W2
__device__ float g_as2[MAXN];
__device__ float g_ad2[MAXN];
__device__ int   g_deg[MAXN];       // zero at load; re-zeroed in scan each run
__device__ int   g_rowptr[MAXN + 1];
__device__ int   g_wpos[MAXN + 1];
__device__ int   g_csrsrc[MAXE];
__device__ float4 g_w1[MAXE];       // layer-1 edge weights (4 heads), CSR order
__device__ int   g_bsums[64];
__device__ float g_v2s[64];         // W2@a_src2
__device__ float g_v2d[64];         // W2@a_dst2
__device__ int   g_cnt1;            // scan barrier counters (self-resetting)
__device__ int   g_cnt2;
__device__ int   g_dhist[64];       // degree histogram bins (zeroed in gemm1_hist)
__device__ int   g_dpos[64];        // per-bin running claim counters
__device__ int   g_perm[MAXN];      // nodes sorted by (clamped) degree

// ---------------- L1: fused GEMM1 (+alpha epilogue) ⊕ edge histogram --------
__global__ void k_gemm1_hist(const float* __restrict__ x, const float* __restrict__ W1,
                             const float* __restrict__ a_src, const float* __restrict__ a_dst,
                             const int* __restrict__ ei, int N, int E, int gemmBlocks) {
    __shared__ float Wsh[128 * 64];   // 32 KB
    __shared__ float xs[128][17];

    if (blockIdx.x >= gemmBlocks) {
        // first hist block also zeroes the sort bins for this run
        if (blockIdx.x == gemmBlocks && threadIdx.x < 128) {
            if (threadIdx.x < 64) g_dhist[threadIdx.x] = 0;
            else                  g_dpos[threadIdx.x - 64] = 0;
        }
        int nb = gridDim.x - gemmBlocks;
        int stride = nb * blockDim.x;
        for (int e = (blockIdx.x - gemmBlocks) * blockDim.x + threadIdx.x; e < E; e += stride)
            atomicAdd(&g_deg[ei[E + e]], 1);
        return;
    }

    int t = threadIdx.x;
    int n0 = blockIdx.x * 128;
    for (int i = t; i < 128 * 64; i += 256) Wsh[i] = W1[i];

    int ng = t >> 3;
    int cg = t & 7;
    float acc[4][8];
#pragma unroll
    for (int r = 0; r < 4; ++r)
#pragma unroll
        for (int j = 0; j < 8; ++j) acc[r][j] = 0.f;

    for (int kt = 0; kt < 128; kt += 16) {
        __syncthreads();
        for (int i = t; i < 128 * 16; i += 256) {
            int n = i >> 4, kk = i & 15;
            int gn = n0 + n;
            xs[n][kk] = (gn < N) ? x[gn * 128 + kt + kk] : 0.f;
        }
        __syncthreads();
#pragma unroll
        for (int kk = 0; kk < 16; ++kk) {
            float wv[8];
#pragma unroll
            for (int j = 0; j < 8; ++j) wv[j] = Wsh[(kt + kk) * 64 + cg * 8 + j];
#pragma unroll
            for (int r = 0; r < 4; ++r) {
                float xv = xs[ng * 4 + r][kk];
#pragma unroll
                for (int j = 0; j < 8; ++j) acc[r][j] = fmaf(xv, wv[j], acc[r][j]);
            }
        }
    }

    float asw[8], adw[8];
#pragma unroll
    for (int j = 0; j < 8; ++j) { asw[j] = __ldg(&a_src[cg * 8 + j]); adw[j] = __ldg(&a_dst[cg * 8 + j]); }

#pragma unroll
    for (int r = 0; r < 4; ++r) {
        int gn = n0 + ng * 4 + r;
        float ps = 0.f, pd = 0.f;
#pragma unroll
        for (int j = 0; j < 8; ++j) { ps = fmaf(acc[r][j], asw[j], ps); pd = fmaf(acc[r][j], adw[j], pd); }
        ps += __shfl_xor_sync(0xffffffffu, ps, 1);
        pd += __shfl_xor_sync(0xffffffffu, pd, 1);
        if (gn < N) {
            float4* dst = reinterpret_cast<float4*>(&g_H1[gn * 64 + cg * 8]);
            dst[0] = make_float4(acc[r][0], acc[r][1], acc[r][2], acc[r][3]);
            dst[1] = make_float4(acc[r][4], acc[r][5], acc[r][6], acc[r][7]);
            if ((cg & 1) == 0) {
                g_as1[gn * 4 + (cg >> 1)] = ps;
                g_ad1[gn * 4 + (cg >> 1)] = pd;
            }
        }
    }
}

// ---------------- L2: single-launch scan (device barrier) ⊕ vpre -------------
// R11 body (measured-good) + one histogram add; bins consumed only by the
// NEXT kernel, so no extra barrier is needed.
__global__ void k_scan_fused(const float* __restrict__ W2,
                             const float* __restrict__ a_src2, const float* __restrict__ a_dst2,
                             int N, int nb) {
    int t = threadIdx.x;
    int bid = blockIdx.x;
    if (bid == nb) {
        if (t < 64) {
            float s2 = 0.f, d2 = 0.f;
#pragma unroll
            for (int j = 0; j < 32; ++j) {
                float wv = W2[t * 32 + j];
                s2 = fmaf(wv, a_src2[j], s2);
                d2 = fmaf(wv, a_dst2[j], d2);
            }
            g_v2s[t] = s2;
            g_v2d[t] = d2;
        }
        return;
    }

    __shared__ int wsum[32];
    __shared__ int sh_off;
    int lane = t & 31, wid = t >> 5;
    int i = bid * 1024 + t;
    int v = (i < N) ? g_deg[i] : 0;
    if (i < N) g_deg[i] = 0;
    // degree histogram for the counting sort (consumed next kernel)
    if (i < N) atomicAdd(&g_dhist[(v < 63) ? v : 63], 1);
    int xx = v;
#pragma unroll
    for (int o = 1; o < 32; o <<= 1) {
        int u = __shfl_up_sync(0xffffffffu, xx, o);
        if (lane >= o) xx += u;
    }
    if (lane == 31) wsum[wid] = xx;
    __syncthreads();
    if (wid == 0) {
        int w = wsum[lane];
#pragma unroll
        for (int o = 1; o < 32; o <<= 1) {
            int u = __shfl_up_sync(0xffffffffu, w, o);
            if (lane >= o) w += u;
        }
        wsum[lane] = w;
    }
    __syncthreads();
    int woff = (wid > 0) ? wsum[wid - 1] : 0;
    int incl = woff + xx;

    if (t == 1023) {
        g_bsums[bid] = incl;
        __threadfence();
        atomicAdd(&g_cnt1, 1);
    }
    if (t == 0) {
        while (*(volatile int*)&g_cnt1 < nb) {}
    }
    __syncthreads();
    __threadfence();

    if (t < 32) {
        int l = t;
        int v1 = (l < nb) ? g_bsums[l] : 0;
        int v2 = (l + 32 < nb) ? g_bsums[l + 32] : 0;
#pragma unroll
        for (int o = 1; o < 32; o <<= 1) {
            int u = __shfl_up_sync(0xffffffffu, v1, o);
            if (l >= o) v1 += u;
        }
        int tot1 = __shfl_sync(0xffffffffu, v1, 31);
#pragma unroll
        for (int o = 1; o < 32; o <<= 1) {
            int u = __shfl_up_sync(0xffffffffu, v2, o);
            if (l >= o) v2 += u;
        }
        int ex;
        if (bid == 0) ex = 0;
        else if (bid - 1 < 32) ex = __shfl_sync(0xffffffffu, v1, bid - 1);
        else ex = tot1 + __shfl_sync(0xffffffffu, v2, bid - 1 - 32);
        if (l == 0) sh_off = ex;
    }
    __syncthreads();
    int off = sh_off;
    if (i < N) {
        int val = incl + off;
        g_rowptr[i + 1] = val;
        g_wpos[i + 1] = val;
    }
    if (bid == 0 && t == 0) { g_rowptr[0] = 0; g_wpos[0] = 0; }

    __syncthreads();
    if (t == 0) {
        int done = atomicAdd(&g_cnt2, 1);
        if (done == nb - 1) { g_cnt1 = 0; g_cnt2 = 0; }
    }
}

// ---------------- L3: CSR fill + layer-1 edge weights ⊕ degree-sort scatter --
// blocks [0,fillBlocks): one edge per thread (as measured).
// blocks [fillBlocks,..): counting-sort scatter. g_dhist and g_rowptr are
// final at kernel start (previous launches), so bin scans are race-free.
__global__ void __launch_bounds__(256) k_fillw(const int* __restrict__ ei, int E, int N, int fillBlocks) {
    if ((int)blockIdx.x >= fillBlocks) {
        __shared__ int sh_ex[64];
        int t = threadIdx.x;
        if (t < 32) {
            int h1 = g_dhist[t];
            int h2 = g_dhist[t + 32];
            int s1 = h1;
#pragma unroll
            for (int o = 1; o < 32; o <<= 1) {
                int u = __shfl_up_sync(0xffffffffu, s1, o);
                if (t >= o) s1 += u;
            }
            int tot1 = __shfl_sync(0xffffffffu, s1, 31);
            int s2 = h2;
#pragma unroll
            for (int o = 1; o < 32; o <<= 1) {
                int u = __shfl_up_sync(0xffffffffu, s2, o);
                if (t >= o) s2 += u;
            }
            sh_ex[t] = s1 - h1;              // exclusive prefix, bins 0..31
            sh_ex[t + 32] = tot1 + s2 - h2;  // bins 32..63
        }
        __syncthreads();
        int i = ((int)blockIdx.x - fillBlocks) * 256 + t;
        if (i < N) {
            int deg = g_rowptr[i + 1] - g_rowptr[i];
            int dcl = (deg < 63) ? deg : 63;
            int pos = sh_ex[dcl] + atomicAdd(&g_dpos[dcl], 1);
            g_perm[pos] = i;
        }
        return;
    }

    int e = blockIdx.x * blockDim.x + threadIdx.x;
    if (e >= E) return;
    int src = ei[e];
    int dst = ei[E + e];
    int p = atomicAdd(&g_wpos[dst], 1);
    g_csrsrc[p] = src;
    float4 as = __ldg(reinterpret_cast<const float4*>(&g_as1[src * 4]));
    float4 ad = __ldg(reinterpret_cast<const float4*>(&g_ad1[dst * 4]));
    float4 w;
    float e0 = as.x + ad.x; w.x = __expf(fmaxf(e0, 0.2f * e0));
    float e1 = as.y + ad.y; w.y = __expf(fmaxf(e1, 0.2f * e1));
    float e2 = as.z + ad.z; w.z = __expf(fmaxf(e2, 0.2f * e2));
    float e3 = as.w + ad.w; w.w = __expf(fmaxf(e3, 0.2f * e3));
    g_w1[p] = w;
}

// ---------------- L4: layer-1 agg: quarter-warp, degree-sorted ---------------
__global__ void k_agg1(const float* __restrict__ b1, int N) {
    int warp = (blockIdx.x * blockDim.x + threadIdx.x) >> 5;
    int lane = threadIdx.x & 31;
    int q = lane >> 3;          // node slot 0..3
    int hl = lane & 7;          // lane-in-group 0..7
    unsigned gmask = 0xffu << (q * 8);
    int idx = warp * 4 + q;
    if (idx >= N) return;
    int node = g_perm[idx];     // degree-sorted: the 4 nodes in a warp match
    int beg = g_rowptr[node], end = g_rowptr[node + 1];
    int ch = hl * 8;            // 8 channels per lane
    int head = hl >> 1;         // 16 channels per head
    const float* w1f = reinterpret_cast<const float*>(g_w1);

    float s = 0.f;
    float a[8] = {0, 0, 0, 0, 0, 0, 0, 0};
    for (int p = beg; p < end; ++p) {
        int src = g_csrsrc[p];
        float w = __ldg(&w1f[p * 4 + head]);
        const float4* hp = reinterpret_cast<const float4*>(&g_H1[src * 64 + ch]);
        float4 h0 = hp[0];
        float4 h1 = hp[1];
        s += w;
        a[0] = fmaf(w, h0.x, a[0]);
        a[1] = fmaf(w, h0.y, a[1]);
        a[2] = fmaf(w, h0.z, a[2]);
        a[3] = fmaf(w, h0.w, a[3]);
        a[4] = fmaf(w, h1.x, a[4]);
        a[5] = fmaf(w, h1.y, a[5]);
        a[6] = fmaf(w, h1.z, a[6]);
        a[7] = fmaf(w, h1.w, a[7]);
    }
    float inv = 1.f / (s + 1e-16f);
    float4 bb0 = *reinterpret_cast<const float4*>(&b1[ch]);
    float4 bb1 = *reinterpret_cast<const float4*>(&b1[ch + 4]);
    float o[8];
    o[0] = fmaf(a[0], inv, bb0.x); o[1] = fmaf(a[1], inv, bb0.y);
    o[2] = fmaf(a[2], inv, bb0.z); o[3] = fmaf(a[3], inv, bb0.w);
    o[4] = fmaf(a[4], inv, bb1.x); o[5] = fmaf(a[5], inv, bb1.y);
    o[6] = fmaf(a[6], inv, bb1.z); o[7] = fmaf(a[7], inv, bb1.w);
#pragma unroll
    for (int j = 0; j < 8; ++j) o[j] = (o[j] > 0.f) ? o[j] : expm1f(o[j]);   // elu
    float4* xo = reinterpret_cast<float4*>(&g_X2[node * 64 + ch]);
    xo[0] = make_float4(o[0], o[1], o[2], o[3]);
    xo[1] = make_float4(o[4], o[5], o[6], o[7]);

    // epilogue: as2/ad2 = X2row . v2 (8-lane group reduction)
    const float4* vsp = reinterpret_cast<const float4*>(&g_v2s[ch]);
    const float4* vdp = reinterpret_cast<const float4*>(&g_v2d[ch]);
    float4 vs0 = vsp[0], vs1 = vsp[1], vd0 = vdp[0], vd1 = vdp[1];
    float ps = o[0]*vs0.x + o[1]*vs0.y + o[2]*vs0.z + o[3]*vs0.w
             + o[4]*vs1.x + o[5]*vs1.y + o[6]*vs1.z + o[7]*vs1.w;
    float pd = o[0]*vd0.x + o[1]*vd0.y + o[2]*vd0.z + o[3]*vd0.w
             + o[4]*vd1.x + o[5]*vd1.y + o[6]*vd1.z + o[7]*vd1.w;
#pragma unroll
    for (int off = 1; off < 8; off <<= 1) {
        ps += __shfl_xor_sync(gmask, ps, off);
        pd += __shfl_xor_sync(gmask, pd, off);
    }
    if (hl == 0) { g_as2[node] = ps; g_ad2[node] = pd; }
}

// ---------------- L5: GEMM2 ---------------------------------------------------
__global__ void k_gemm2(const float* __restrict__ W2, int N) {
    __shared__ float Wsh[64 * 32];
    __shared__ float xs[128][65];
    int t = threadIdx.x;
    int n0 = blockIdx.x * 128;
    for (int i = t; i < 64 * 32; i += 128) Wsh[i] = W2[i];
    for (int i = t; i < 128 * 64; i += 128) {
        int n = i >> 6, k = i & 63;
        int gn = n0 + n;
        xs[n][k] = (gn < N) ? g_X2[gn * 64 + k] : 0.f;
    }
    __syncthreads();
    int ng = t >> 2;
    int cg = t & 3;
    float acc[4][8];
#pragma unroll
    for (int r = 0; r < 4; ++r)
#pragma unroll
        for (int j = 0; j < 8; ++j) acc[r][j] = 0.f;
#pragma unroll 4
    for (int k = 0; k < 64; ++k) {
        float wv[8];
#pragma unroll
        for (int j = 0; j < 8; ++j) wv[j] = Wsh[k * 32 + cg * 8 + j];
#pragma unroll
        for (int r = 0; r < 4; ++r) {
            float xv = xs[ng * 4 + r][k];
#pragma unroll
            for (int j = 0; j < 8; ++j) acc[r][j] = fmaf(xv, wv[j], acc[r][j]);
        }
    }
#pragma unroll
    for (int r = 0; r < 4; ++r) {
        int gn = n0 + ng * 4 + r;
        if (gn < N) {
            float4* dst = reinterpret_cast<float4*>(&g_H2[gn * 32 + cg * 8]);
            dst[0] = make_float4(acc[r][0], acc[r][1], acc[r][2], acc[r][3]);
            dst[1] = make_float4(acc[r][4], acc[r][5], acc[r][6], acc[r][7]);
        }
    }
}

// ---------------- L6: layer-2 agg: quarter-warp, degree-sorted ---------------
__global__ void k_agg2(const float* __restrict__ b2, float* __restrict__ out, int N) {
    int warp = (blockIdx.x * blockDim.x + threadIdx.x) >> 5;
    int lane = threadIdx.x & 31;
    int q = lane >> 3;
    int hl = lane & 7;
    int idx = warp * 4 + q;
    if (idx >= N) return;
    int node = g_perm[idx];
    int beg = g_rowptr[node], end = g_rowptr[node + 1];
    int ch = hl * 4;
    float adv = g_ad2[node];

    float s = 0.f;
    float a0 = 0.f, a1 = 0.f, a2 = 0.f, a3 = 0.f;
    for (int p = beg; p < end; ++p) {
        int src = g_csrsrc[p];
        float e = __ldg(&g_as2[src]) + adv;
        float4 h = *reinterpret_cast<const float4*>(&g_H2[src * 32 + ch]);
        float w = __expf(fmaxf(e, 0.2f * e));
        s += w;
        a0 = fmaf(w, h.x, a0);
        a1 = fmaf(w, h.y, a1);
        a2 = fmaf(w, h.z, a2);
        a3 = fmaf(w, h.w, a3);
    }
    float inv = 1.f / (s + 1e-16f);
    float4 bb = *reinterpret_cast<const float4*>(&b2[ch]);
    float4 o;
    o.x = fmaf(a0, inv, bb.x);
    o.y = fmaf(a1, inv, bb.y);
    o.z = fmaf(a2, inv, bb.z);
    o.w = fmaf(a3, inv, bb.w);
    *reinterpret_cast<float4*>(&out[node * 32 + ch]) = o;
}

// ---------------- launch -----------------------------------------------------
extern "C" void kernel_launch(void* const* d_in, const int* in_sizes, int n_in,
                              void* d_out, int out_size) {
    const float* x      = (const float*)d_in[0];
    const int*   ei     = (const int*)  d_in[1];
    const float* W1     = (const float*)d_in[2];
    const float* a_src1 = (const float*)d_in[3];
    const float* a_dst1 = (const float*)d_in[4];
    const float* b1     = (const float*)d_in[5];
    const float* W2     = (const float*)d_in[6];
    const float* a_src2 = (const float*)d_in[7];
    const float* a_dst2 = (const float*)d_in[8];
    const float* b2     = (const float*)d_in[9];

    int N = in_sizes[0] / 128;
    int E = in_sizes[1] / 2;
    int nb = (N + 1023) / 1024;

    int gemmBlocks = (N + 127) / 128;
    int histBlocks = 1184;
    int fillBlocks = (E + 255) / 256;
    int scatBlocks = (N + 255) / 256;
    int aggWarps = (N + 3) / 4;          // 4 nodes per warp

    // L1: GEMM1(+alphas1) overlapped with edge histogram (+bin zeroing)
    k_gemm1_hist<<<gemmBlocks + histBlocks, 256>>>(x, W1, a_src1, a_dst1, ei, N, E, gemmBlocks);
    // L2: single-launch scan + degree histogram + v2 projections
    k_scan_fused<<<nb + 1, 1024>>>(W2, a_src2, a_dst2, N, nb);
    // L3: CSR fill + layer-1 edge weights, overlapped with sort scatter
    k_fillw<<<fillBlocks + scatBlocks, 256>>>(ei, E, N, fillBlocks);
    // L4: layer-1 aggregation (+elu, +as2/ad2), degree-balanced
    k_agg1<<<(aggWarps * 32 + 255) / 256, 256>>>(b1, N);
    // L5: GEMM2
    k_gemm2<<<(N + 127) / 128, 128>>>(W2, N);
    // L6: layer-2 aggregation (inline w2), degree-balanced
    k_agg2<<<(aggWarps * 32 + 255) / 256, 256>>>(b2, (float*)d_out, N);
}

// round 16
// speedup vs baseline: 1.2340x; 1.2340x over previous
#include <cuda_runtime.h>

// ---------------- static scratch (no dynamic allocation allowed) ------------
#define MAXN 50016
#define MAXE 800000

__device__ float g_H1[MAXN * 64];   // layer-1 features x@W1
__device__ float g_as1[MAXN * 4];   // alpha_src layer1 per head
__device__ float g_ad1[MAXN * 4];   // alpha_dst layer1 per head
__device__ float g_X2[MAXN * 64];   // elu(gat1 output) = input to layer2
__device__ float g_H2[MAXN * 32];   // layer-2 features X2@W2
__device__ float g_as2[MAXN];
__device__ float g_ad2[MAXN];
__device__ int   g_deg[MAXN];       // zero at load; re-zeroed in scan each run
__device__ int   g_rowptr[MAXN + 1];
__device__ int   g_wpos[MAXN + 1];
__device__ int   g_csrsrc[MAXE];
__device__ int   g_bsums[64];
__device__ float g_v2s[64];         // W2@a_src2
__device__ float g_v2d[64];         // W2@a_dst2
__device__ int   g_cnt1;            // scan barrier counters (self-resetting)
__device__ int   g_cnt2;

// ---------------- L1: fused GEMM1 (+alpha epilogue) ⊕ edge histogram --------
__global__ void k_gemm1_hist(const float* __restrict__ x, const float* __restrict__ W1,
                             const float* __restrict__ a_src, const float* __restrict__ a_dst,
                             const int* __restrict__ ei, int N, int E, int gemmBlocks) {
    __shared__ float Wsh[128 * 64];   // 32 KB
    __shared__ float xs[128][17];

    if (blockIdx.x >= gemmBlocks) {
        int nb = gridDim.x - gemmBlocks;
        int stride = nb * blockDim.x;
        for (int e = (blockIdx.x - gemmBlocks) * blockDim.x + threadIdx.x; e < E; e += stride)
            atomicAdd(&g_deg[ei[E + e]], 1);
        return;
    }

    int t = threadIdx.x;
    int n0 = blockIdx.x * 128;
    for (int i = t; i < 128 * 64; i += 256) Wsh[i] = W1[i];

    int ng = t >> 3;
    int cg = t & 7;
    float acc[4][8];
#pragma unroll
    for (int r = 0; r < 4; ++r)
#pragma unroll
        for (int j = 0; j < 8; ++j) acc[r][j] = 0.f;

    for (int kt = 0; kt < 128; kt += 16) {
        __syncthreads();
        for (int i = t; i < 128 * 16; i += 256) {
            int n = i >> 4, kk = i & 15;
            int gn = n0 + n;
            xs[n][kk] = (gn < N) ? x[gn * 128 + kt + kk] : 0.f;
        }
        __syncthreads();
#pragma unroll
        for (int kk = 0; kk < 16; ++kk) {
            float wv[8];
#pragma unroll
            for (int j = 0; j < 8; ++j) wv[j] = Wsh[(kt + kk) * 64 + cg * 8 + j];
#pragma unroll
            for (int r = 0; r < 4; ++r) {
                float xv = xs[ng * 4 + r][kk];
#pragma unroll
                for (int j = 0; j < 8; ++j) acc[r][j] = fmaf(xv, wv[j], acc[r][j]);
            }
        }
    }

    float asw[8], adw[8];
#pragma unroll
    for (int j = 0; j < 8; ++j) { asw[j] = __ldg(&a_src[cg * 8 + j]); adw[j] = __ldg(&a_dst[cg * 8 + j]); }

#pragma unroll
    for (int r = 0; r < 4; ++r) {
        int gn = n0 + ng * 4 + r;
        float ps = 0.f, pd = 0.f;
#pragma unroll
        for (int j = 0; j < 8; ++j) { ps = fmaf(acc[r][j], asw[j], ps); pd = fmaf(acc[r][j], adw[j], pd); }
        ps += __shfl_xor_sync(0xffffffffu, ps, 1);
        pd += __shfl_xor_sync(0xffffffffu, pd, 1);
        if (gn < N) {
            float4* dst = reinterpret_cast<float4*>(&g_H1[gn * 64 + cg * 8]);
            dst[0] = make_float4(acc[r][0], acc[r][1], acc[r][2], acc[r][3]);
            dst[1] = make_float4(acc[r][4], acc[r][5], acc[r][6], acc[r][7]);
            if ((cg & 1) == 0) {
                g_as1[gn * 4 + (cg >> 1)] = ps;
                g_ad1[gn * 4 + (cg >> 1)] = pd;
            }
        }
    }
}

// ---------------- L2: single-launch scan (device barrier) ⊕ vpre -------------
__global__ void k_scan_fused(const float* __restrict__ W2,
                             const float* __restrict__ a_src2, const float* __restrict__ a_dst2,
                             int N, int nb) {
    int t = threadIdx.x;
    int bid = blockIdx.x;
    if (bid == nb) {
        if (t < 64) {
            float s2 = 0.f, d2 = 0.f;
#pragma unroll
            for (int j = 0; j < 32; ++j) {
                float wv = W2[t * 32 + j];
                s2 = fmaf(wv, a_src2[j], s2);
                d2 = fmaf(wv, a_dst2[j], d2);
            }
            g_v2s[t] = s2;
            g_v2d[t] = d2;
        }
        return;
    }

    __shared__ int wsum[32];
    __shared__ int sh_off;
    int lane = t & 31, wid = t >> 5;
    int i = bid * 1024 + t;
    int v = (i < N) ? g_deg[i] : 0;
    if (i < N) g_deg[i] = 0;
    int xx = v;
#pragma unroll
    for (int o = 1; o < 32; o <<= 1) {
        int u = __shfl_up_sync(0xffffffffu, xx, o);
        if (lane >= o) xx += u;
    }
    if (lane == 31) wsum[wid] = xx;
    __syncthreads();
    if (wid == 0) {
        int w = wsum[lane];
#pragma unroll
        for (int o = 1; o < 32; o <<= 1) {
            int u = __shfl_up_sync(0xffffffffu, w, o);
            if (lane >= o) w += u;
        }
        wsum[lane] = w;
    }
    __syncthreads();
    int woff = (wid > 0) ? wsum[wid - 1] : 0;
    int incl = woff + xx;

    if (t == 1023) {
        g_bsums[bid] = incl;
        __threadfence();
        atomicAdd(&g_cnt1, 1);
    }
    if (t == 0) {
        while (*(volatile int*)&g_cnt1 < nb) {}
    }
    __syncthreads();
    __threadfence();

    if (t < 32) {
        int l = t;
        int v1 = (l < nb) ? g_bsums[l] : 0;
        int v2 = (l + 32 < nb) ? g_bsums[l + 32] : 0;
#pragma unroll
        for (int o = 1; o < 32; o <<= 1) {
            int u = __shfl_up_sync(0xffffffffu, v1, o);
            if (l >= o) v1 += u;
        }
        int tot1 = __shfl_sync(0xffffffffu, v1, 31);
#pragma unroll
        for (int o = 1; o < 32; o <<= 1) {
            int u = __shfl_up_sync(0xffffffffu, v2, o);
            if (l >= o) v2 += u;
        }
        int ex;
        if (bid == 0) ex = 0;
        else if (bid - 1 < 32) ex = __shfl_sync(0xffffffffu, v1, bid - 1);
        else ex = tot1 + __shfl_sync(0xffffffffu, v2, bid - 1 - 32);
        if (l == 0) sh_off = ex;
    }
    __syncthreads();
    int off = sh_off;
    if (i < N) {
        int val = incl + off;
        g_rowptr[i + 1] = val;
        g_wpos[i + 1] = val;
    }
    if (bid == 0 && t == 0) { g_rowptr[0] = 0; g_wpos[0] = 0; }

    __syncthreads();
    if (t == 0) {
        int done = atomicAdd(&g_cnt2, 1);
        if (done == nb - 1) { g_cnt1 = 0; g_cnt2 = 0; }
    }
}

// ---------------- L3: CSR fill (lean, measured 15.9us) ------------------------
__global__ void __launch_bounds__(256) k_fill(const int* __restrict__ ei, int E) {
    int e = blockIdx.x * blockDim.x + threadIdx.x;
    if (e < E) {
        int src = ei[e];
        int dst = ei[E + e];
        int p = atomicAdd(&g_wpos[dst], 1);
        g_csrsrc[p] = src;
    }
}

// ---------------- L4: layer-1 agg: quarter-warp, inline edge weights ---------
// lane hl covers 8 channels [hl*8, hl*8+8), head = hl>>1.
// w computed inline (agg2's proven pattern): gather as1[src] (4B, replaces the
// w1 read), hoisted ad1[node], lrelu + exp per edge.
__global__ void k_agg1(const float* __restrict__ b1, int N) {
    int warp = (blockIdx.x * blockDim.x + threadIdx.x) >> 5;
    int lane = threadIdx.x & 31;
    int q = lane >> 3;          // node slot 0..3
    int hl = lane & 7;          // lane-in-group 0..7
    unsigned gmask = 0xffu << (q * 8);
    int node = warp * 4 + q;
    if (node >= N) return;
    int beg = g_rowptr[node], end = g_rowptr[node + 1];
    int ch = hl * 8;            // 8 channels per lane
    int head = hl >> 1;         // 16 channels per head
    float adv = g_ad1[node * 4 + head];

    float s = 0.f;
    float a[8] = {0, 0, 0, 0, 0, 0, 0, 0};
    for (int p = beg; p < end; ++p) {
        int src = g_csrsrc[p];
        float e = __ldg(&g_as1[src * 4 + head]) + adv;
        const float4* hp = reinterpret_cast<const float4*>(&g_H1[src * 64 + ch]);
        float4 h0 = hp[0];
        float4 h1 = hp[1];
        float w = __expf(fmaxf(e, 0.2f * e));   // exp(leaky_relu(e))
        s += w;
        a[0] = fmaf(w, h0.x, a[0]);
        a[1] = fmaf(w, h0.y, a[1]);
        a[2] = fmaf(w, h0.z, a[2]);
        a[3] = fmaf(w, h0.w, a[3]);
        a[4] = fmaf(w, h1.x, a[4]);
        a[5] = fmaf(w, h1.y, a[5]);
        a[6] = fmaf(w, h1.z, a[6]);
        a[7] = fmaf(w, h1.w, a[7]);
    }
    float inv = 1.f / (s + 1e-16f);
    float4 bb0 = *reinterpret_cast<const float4*>(&b1[ch]);
    float4 bb1 = *reinterpret_cast<const float4*>(&b1[ch + 4]);
    float o[8];
    o[0] = fmaf(a[0], inv, bb0.x); o[1] = fmaf(a[1], inv, bb0.y);
    o[2] = fmaf(a[2], inv, bb0.z); o[3] = fmaf(a[3], inv, bb0.w);
    o[4] = fmaf(a[4], inv, bb1.x); o[5] = fmaf(a[5], inv, bb1.y);
    o[6] = fmaf(a[6], inv, bb1.z); o[7] = fmaf(a[7], inv, bb1.w);
#pragma unroll
    for (int j = 0; j < 8; ++j) o[j] = (o[j] > 0.f) ? o[j] : expm1f(o[j]);   // elu
    float4* xo = reinterpret_cast<float4*>(&g_X2[node * 64 + ch]);
    xo[0] = make_float4(o[0], o[1], o[2], o[3]);
    xo[1] = make_float4(o[4], o[5], o[6], o[7]);

    // epilogue: as2/ad2 = X2row . v2 (8-lane group reduction)
    const float4* vsp = reinterpret_cast<const float4*>(&g_v2s[ch]);
    const float4* vdp = reinterpret_cast<const float4*>(&g_v2d[ch]);
    float4 vs0 = vsp[0], vs1 = vsp[1], vd0 = vdp[0], vd1 = vdp[1];
    float ps = o[0]*vs0.x + o[1]*vs0.y + o[2]*vs0.z + o[3]*vs0.w
             + o[4]*vs1.x + o[5]*vs1.y + o[6]*vs1.z + o[7]*vs1.w;
    float pd = o[0]*vd0.x + o[1]*vd0.y + o[2]*vd0.z + o[3]*vd0.w
             + o[4]*vd1.x + o[5]*vd1.y + o[6]*vd1.z + o[7]*vd1.w;
#pragma unroll
    for (int off = 1; off < 8; off <<= 1) {
        ps += __shfl_xor_sync(gmask, ps, off);
        pd += __shfl_xor_sync(gmask, pd, off);
    }
    if (hl == 0) { g_as2[node] = ps; g_ad2[node] = pd; }
}

// ---------------- L5: GEMM2 ---------------------------------------------------
__global__ void k_gemm2(const float* __restrict__ W2, int N) {
    __shared__ float Wsh[64 * 32];
    __shared__ float xs[128][65];
    int t = threadIdx.x;
    int n0 = blockIdx.x * 128;
    for (int i = t; i < 64 * 32; i += 128) Wsh[i] = W2[i];
    for (int i = t; i < 128 * 64; i += 128) {
        int n = i >> 6, k = i & 63;
        int gn = n0 + n;
        xs[n][k] = (gn < N) ? g_X2[gn * 64 + k] : 0.f;
    }
    __syncthreads();
    int ng = t >> 2;
    int cg = t & 3;
    float acc[4][8];
#pragma unroll
    for (int r = 0; r < 4; ++r)
#pragma unroll
        for (int j = 0; j < 8; ++j) acc[r][j] = 0.f;
#pragma unroll 4
    for (int k = 0; k < 64; ++k) {
        float wv[8];
#pragma unroll
        for (int j = 0; j < 8; ++j) wv[j] = Wsh[k * 32 + cg * 8 + j];
#pragma unroll
        for (int r = 0; r < 4; ++r) {
            float xv = xs[ng * 4 + r][k];
#pragma unroll
            for (int j = 0; j < 8; ++j) acc[r][j] = fmaf(xv, wv[j], acc[r][j]);
        }
    }
#pragma unroll
    for (int r = 0; r < 4; ++r) {
        int gn = n0 + ng * 4 + r;
        if (gn < N) {
            float4* dst = reinterpret_cast<float4*>(&g_H2[gn * 32 + cg * 8]);
            dst[0] = make_float4(acc[r][0], acc[r][1], acc[r][2], acc[r][3]);
            dst[1] = make_float4(acc[r][4], acc[r][5], acc[r][6], acc[r][7]);
        }
    }
}

// ---------------- L6: layer-2 agg: quarter-warp, inline w --------------------
__global__ void k_agg2(const float* __restrict__ b2, float* __restrict__ out, int N) {
    int warp = (blockIdx.x * blockDim.x + threadIdx.x) >> 5;
    int lane = threadIdx.x & 31;
    int q = lane >> 3;
    int hl = lane & 7;
    int node = warp * 4 + q;
    if (node >= N) return;
    int beg = g_rowptr[node], end = g_rowptr[node + 1];
    int ch = hl * 4;
    float adv = g_ad2[node];

    float s = 0.f;
    float a0 = 0.f, a1 = 0.f, a2 = 0.f, a3 = 0.f;
    for (int p = beg; p < end; ++p) {
        int src = g_csrsrc[p];
        float e = __ldg(&g_as2[src]) + adv;
        float4 h = *reinterpret_cast<const float4*>(&g_H2[src * 32 + ch]);
        float w = __expf(fmaxf(e, 0.2f * e));
        s += w;
        a0 = fmaf(w, h.x, a0);
        a1 = fmaf(w, h.y, a1);
        a2 = fmaf(w, h.z, a2);
        a3 = fmaf(w, h.w, a3);
    }
    float inv = 1.f / (s + 1e-16f);
    float4 bb = *reinterpret_cast<const float4*>(&b2[ch]);
    float4 o;
    o.x = fmaf(a0, inv, bb.x);
    o.y = fmaf(a1, inv, bb.y);
    o.z = fmaf(a2, inv, bb.z);
    o.w = fmaf(a3, inv, bb.w);
    *reinterpret_cast<float4*>(&out[node * 32 + ch]) = o;
}

// ---------------- launch -----------------------------------------------------
extern "C" void kernel_launch(void* const* d_in, const int* in_sizes, int n_in,
                              void* d_out, int out_size) {
    const float* x      = (const float*)d_in[0];
    const int*   ei     = (const int*)  d_in[1];
    const float* W1     = (const float*)d_in[2];
    const float* a_src1 = (const float*)d_in[3];
    const float* a_dst1 = (const float*)d_in[4];
    const float* b1     = (const float*)d_in[5];
    const float* W2     = (const float*)d_in[6];
    const float* a_src2 = (const float*)d_in[7];
    const float* a_dst2 = (const float*)d_in[8];
    const float* b2     = (const float*)d_in[9];

    int N = in_sizes[0] / 128;
    int E = in_sizes[1] / 2;
    int nb = (N + 1023) / 1024;

    int gemmBlocks = (N + 127) / 128;
    int histBlocks = 1184;
    int aggWarps = (N + 3) / 4;          // 4 nodes per warp

    // L1: GEMM1(+alphas1) overlapped with edge histogram
    k_gemm1_hist<<<gemmBlocks + histBlocks, 256>>>(x, W1, a_src1, a_dst1, ei, N, E, gemmBlocks);
    // L2: single-launch scan (device barrier) + v2 projections
    k_scan_fused<<<nb + 1, 1024>>>(W2, a_src2, a_dst2, N, nb);
    // L3: CSR fill (lean)
    k_fill<<<(E + 255) / 256, 256>>>(ei, E);
    // L4: layer-1 aggregation (inline w, +elu, +as2/ad2)
    k_agg1<<<(aggWarps * 32 + 255) / 256, 256>>>(b1, N);
    // L5: GEMM2
    k_gemm2<<<(N + 127) / 128, 128>>>(W2, N);
    // L6: layer-2 aggregation (inline w2)
    k_agg2<<<(aggWarps * 32 + 255) / 256, 256>>>(b2, (float*)d_out, N);
}

// round 17
// speedup vs baseline: 1.2822x; 1.0390x over previous
#include <cuda_runtime.h>

// ---------------- static scratch (no dynamic allocation allowed) ------------
#define MAXN 50016
#define MAXE 800000

__device__ float g_H1[MAXN * 64];   // layer-1 features x@W1
__device__ float g_as1[MAXN * 4];   // alpha_src layer1 per head
__device__ float g_ad1[MAXN * 4];   // alpha_dst layer1 per head
__device__ float g_X2[MAXN * 64];   // elu(gat1 output) = input to layer2
__device__ float g_H2[MAXN * 32];   // layer-2 features X2@W2
__device__ float g_as2[MAXN];
__device__ float g_ad2[MAXN];
__device__ int   g_deg[MAXN];       // zero at load; re-zeroed in scan each run
__device__ int   g_rowptr[MAXN + 1];
__device__ int   g_wpos[MAXN + 1];
__device__ int   g_csrsrc[MAXE];
__device__ int   g_bsums[64];
__device__ float g_v2s[64];         // W2@a_src2
__device__ float g_v2d[64];         // W2@a_dst2

// ---------------- A: GEMM1 standalone (stream 2) + alpha epilogue ------------
__global__ void k_gemm1(const float* __restrict__ x, const float* __restrict__ W1,
                        const float* __restrict__ a_src, const float* __restrict__ a_dst, int N) {
    __shared__ float Wsh[128 * 64];   // 32 KB
    __shared__ float xs[128][17];

    int t = threadIdx.x;
    int n0 = blockIdx.x * 128;
    for (int i = t; i < 128 * 64; i += 256) Wsh[i] = W1[i];

    int ng = t >> 3;
    int cg = t & 7;
    float acc[4][8];
#pragma unroll
    for (int r = 0; r < 4; ++r)
#pragma unroll
        for (int j = 0; j < 8; ++j) acc[r][j] = 0.f;

    for (int kt = 0; kt < 128; kt += 16) {
        __syncthreads();
        for (int i = t; i < 128 * 16; i += 256) {
            int n = i >> 4, kk = i & 15;
            int gn = n0 + n;
            xs[n][kk] = (gn < N) ? x[gn * 128 + kt + kk] : 0.f;
        }
        __syncthreads();
#pragma unroll
        for (int kk = 0; kk < 16; ++kk) {
            float wv[8];
#pragma unroll
            for (int j = 0; j < 8; ++j) wv[j] = Wsh[(kt + kk) * 64 + cg * 8 + j];
#pragma unroll
            for (int r = 0; r < 4; ++r) {
                float xv = xs[ng * 4 + r][kk];
#pragma unroll
                for (int j = 0; j < 8; ++j) acc[r][j] = fmaf(xv, wv[j], acc[r][j]);
            }
        }
    }

    float asw[8], adw[8];
#pragma unroll
    for (int j = 0; j < 8; ++j) { asw[j] = __ldg(&a_src[cg * 8 + j]); adw[j] = __ldg(&a_dst[cg * 8 + j]); }

#pragma unroll
    for (int r = 0; r < 4; ++r) {
        int gn = n0 + ng * 4 + r;
        float ps = 0.f, pd = 0.f;
#pragma unroll
        for (int j = 0; j < 8; ++j) { ps = fmaf(acc[r][j], asw[j], ps); pd = fmaf(acc[r][j], adw[j], pd); }
        ps += __shfl_xor_sync(0xffffffffu, ps, 1);
        pd += __shfl_xor_sync(0xffffffffu, pd, 1);
        if (gn < N) {
            float4* dst = reinterpret_cast<float4*>(&g_H1[gn * 64 + cg * 8]);
            dst[0] = make_float4(acc[r][0], acc[r][1], acc[r][2], acc[r][3]);
            dst[1] = make_float4(acc[r][4], acc[r][5], acc[r][6], acc[r][7]);
            if ((cg & 1) == 0) {
                g_as1[gn * 4 + (cg >> 1)] = ps;
                g_ad1[gn * 4 + (cg >> 1)] = pd;
            }
        }
    }
}

// ---------------- B1: edge histogram (stream 0) -------------------------------
__global__ void __launch_bounds__(256) k_hist(const int* __restrict__ ei, int E) {
    int e = blockIdx.x * blockDim.x + threadIdx.x;
    if (e < E) atomicAdd(&g_deg[ei[E + e]], 1);
}

// ---------------- B2: per-tile scan (non-spinning) ⊕ vpre ---------------------
__global__ void k_scan_block(const float* __restrict__ W2,
                             const float* __restrict__ a_src2, const float* __restrict__ a_dst2,
                             int N, int nb) {
    int t = threadIdx.x;
    if ((int)blockIdx.x == nb) {
        if (t < 64) {
            float s2 = 0.f, d2 = 0.f;
#pragma unroll
            for (int j = 0; j < 32; ++j) {
                float wv = W2[t * 32 + j];
                s2 = fmaf(wv, a_src2[j], s2);
                d2 = fmaf(wv, a_dst2[j], d2);
            }
            g_v2s[t] = s2;
            g_v2d[t] = d2;
        }
        return;
    }
    __shared__ int wsum[32];
    int lane = t & 31, wid = t >> 5;
    int i = blockIdx.x * 1024 + t;
    int v = (i < N) ? g_deg[i] : 0;
    if (i < N) g_deg[i] = 0;
    int xx = v;
#pragma unroll
    for (int o = 1; o < 32; o <<= 1) {
        int u = __shfl_up_sync(0xffffffffu, xx, o);
        if (lane >= o) xx += u;
    }
    if (lane == 31) wsum[wid] = xx;
    __syncthreads();
    if (wid == 0) {
        int w = wsum[lane];
#pragma unroll
        for (int o = 1; o < 32; o <<= 1) {
            int u = __shfl_up_sync(0xffffffffu, w, o);
            if (lane >= o) w += u;
        }
        wsum[lane] = w;
    }
    __syncthreads();
    int woff = (wid > 0) ? wsum[wid - 1] : 0;
    int incl = woff + xx;
    if (i < N) g_rowptr[i + 1] = incl;
    if (t == 1023) g_bsums[blockIdx.x] = incl;
}

// ---------------- B3: add tile offsets ----------------------------------------
__global__ void k_scan_add(int N, int nb) {
    __shared__ int sh_off;
    int t = threadIdx.x;
    if (t < 32) {
        int lane = t;
        int v1 = (lane < nb) ? g_bsums[lane] : 0;
        int v2 = (lane + 32 < nb) ? g_bsums[lane + 32] : 0;
#pragma unroll
        for (int o = 1; o < 32; o <<= 1) {
            int u = __shfl_up_sync(0xffffffffu, v1, o);
            if (lane >= o) v1 += u;
        }
        int tot1 = __shfl_sync(0xffffffffu, v1, 31);
#pragma unroll
        for (int o = 1; o < 32; o <<= 1) {
            int u = __shfl_up_sync(0xffffffffu, v2, o);
            if (lane >= o) v2 += u;
        }
        int bid = blockIdx.x;
        int ex;
        if (bid == 0) ex = 0;
        else if (bid - 1 < 32) ex = __shfl_sync(0xffffffffu, v1, bid - 1);
        else ex = tot1 + __shfl_sync(0xffffffffu, v2, bid - 1 - 32);
        if (lane == 0) sh_off = ex;
    }
    __syncthreads();
    int off = sh_off;
    int i = blockIdx.x * 1024 + t;
    if (i < N) {
        int val = g_rowptr[i + 1] + off;
        g_rowptr[i + 1] = val;
        g_wpos[i + 1] = val;
    }
    if (blockIdx.x == 0 && t == 0) { g_rowptr[0] = 0; g_wpos[0] = 0; }
}

// ---------------- B4: CSR fill (lean) -----------------------------------------
__global__ void __launch_bounds__(256) k_fill(const int* __restrict__ ei, int E) {
    int e = blockIdx.x * blockDim.x + threadIdx.x;
    if (e < E) {
        int src = ei[e];
        int dst = ei[E + e];
        int p = atomicAdd(&g_wpos[dst], 1);
        g_csrsrc[p] = src;
    }
}

// ---------------- C: layer-1 agg: quarter-warp, inline edge weights ----------
__global__ void k_agg1(const float* __restrict__ b1, int N) {
    int warp = (blockIdx.x * blockDim.x + threadIdx.x) >> 5;
    int lane = threadIdx.x & 31;
    int q = lane >> 3;          // node slot 0..3
    int hl = lane & 7;          // lane-in-group 0..7
    unsigned gmask = 0xffu << (q * 8);
    int node = warp * 4 + q;
    if (node >= N) return;
    int beg = g_rowptr[node], end = g_rowptr[node + 1];
    int ch = hl * 8;            // 8 channels per lane
    int head = hl >> 1;         // 16 channels per head
    float adv = g_ad1[node * 4 + head];

    float s = 0.f;
    float a[8] = {0, 0, 0, 0, 0, 0, 0, 0};
    for (int p = beg; p < end; ++p) {
        int src = g_csrsrc[p];
        float e = __ldg(&g_as1[src * 4 + head]) + adv;
        const float4* hp = reinterpret_cast<const float4*>(&g_H1[src * 64 + ch]);
        float4 h0 = hp[0];
        float4 h1 = hp[1];
        float w = __expf(fmaxf(e, 0.2f * e));   // exp(leaky_relu(e))
        s += w;
        a[0] = fmaf(w, h0.x, a[0]);
        a[1] = fmaf(w, h0.y, a[1]);
        a[2] = fmaf(w, h0.z, a[2]);
        a[3] = fmaf(w, h0.w, a[3]);
        a[4] = fmaf(w, h1.x, a[4]);
        a[5] = fmaf(w, h1.y, a[5]);
        a[6] = fmaf(w, h1.z, a[6]);
        a[7] = fmaf(w, h1.w, a[7]);
    }
    float inv = 1.f / (s + 1e-16f);
    float4 bb0 = *reinterpret_cast<const float4*>(&b1[ch]);
    float4 bb1 = *reinterpret_cast<const float4*>(&b1[ch + 4]);
    float o[8];
    o[0] = fmaf(a[0], inv, bb0.x); o[1] = fmaf(a[1], inv, bb0.y);
    o[2] = fmaf(a[2], inv, bb0.z); o[3] = fmaf(a[3], inv, bb0.w);
    o[4] = fmaf(a[4], inv, bb1.x); o[5] = fmaf(a[5], inv, bb1.y);
    o[6] = fmaf(a[6], inv, bb1.z); o[7] = fmaf(a[7], inv, bb1.w);
#pragma unroll
    for (int j = 0; j < 8; ++j) o[j] = (o[j] > 0.f) ? o[j] : expm1f(o[j]);   // elu
    float4* xo = reinterpret_cast<float4*>(&g_X2[node * 64 + ch]);
    xo[0] = make_float4(o[0], o[1], o[2], o[3]);
    xo[1] = make_float4(o[4], o[5], o[6], o[7]);

    // epilogue: as2/ad2 = X2row . v2 (8-lane group reduction)
    const float4* vsp = reinterpret_cast<const float4*>(&g_v2s[ch]);
    const float4* vdp = reinterpret_cast<const float4*>(&g_v2d[ch]);
    float4 vs0 = vsp[0], vs1 = vsp[1], vd0 = vdp[0], vd1 = vdp[1];
    float ps = o[0]*vs0.x + o[1]*vs0.y + o[2]*vs0.z + o[3]*vs0.w
             + o[4]*vs1.x + o[5]*vs1.y + o[6]*vs1.z + o[7]*vs1.w;
    float pd = o[0]*vd0.x + o[1]*vd0.y + o[2]*vd0.z + o[3]*vd0.w
             + o[4]*vd1.x + o[5]*vd1.y + o[6]*vd1.z + o[7]*vd1.w;
#pragma unroll
    for (int off = 1; off < 8; off <<= 1) {
        ps += __shfl_xor_sync(gmask, ps, off);
        pd += __shfl_xor_sync(gmask, pd, off);
    }
    if (hl == 0) { g_as2[node] = ps; g_ad2[node] = pd; }
}

// ---------------- D: GEMM2 -----------------------------------------------------
__global__ void k_gemm2(const float* __restrict__ W2, int N) {
    __shared__ float Wsh[64 * 32];
    __shared__ float xs[128][65];
    int t = threadIdx.x;
    int n0 = blockIdx.x * 128;
    for (int i = t; i < 64 * 32; i += 128) Wsh[i] = W2[i];
    for (int i = t; i < 128 * 64; i += 128) {
        int n = i >> 6, k = i & 63;
        int gn = n0 + n;
        xs[n][k] = (gn < N) ? g_X2[gn * 64 + k] : 0.f;
    }
    __syncthreads();
    int ng = t >> 2;
    int cg = t & 3;
    float acc[4][8];
#pragma unroll
    for (int r = 0; r < 4; ++r)
#pragma unroll
        for (int j = 0; j < 8; ++j) acc[r][j] = 0.f;
#pragma unroll 4
    for (int k = 0; k < 64; ++k) {
        float wv[8];
#pragma unroll
        for (int j = 0; j < 8; ++j) wv[j] = Wsh[k * 32 + cg * 8 + j];
#pragma unroll
        for (int r = 0; r < 4; ++r) {
            float xv = xs[ng * 4 + r][k];
#pragma unroll
            for (int j = 0; j < 8; ++j) acc[r][j] = fmaf(xv, wv[j], acc[r][j]);
        }
    }
#pragma unroll
    for (int r = 0; r < 4; ++r) {
        int gn = n0 + ng * 4 + r;
        if (gn < N) {
            float4* dst = reinterpret_cast<float4*>(&g_H2[gn * 32 + cg * 8]);
            dst[0] = make_float4(acc[r][0], acc[r][1], acc[r][2], acc[r][3]);
            dst[1] = make_float4(acc[r][4], acc[r][5], acc[r][6], acc[r][7]);
        }
    }
}

// ---------------- E: layer-2 agg: quarter-warp, inline w ----------------------
__global__ void k_agg2(const float* __restrict__ b2, float* __restrict__ out, int N) {
    int warp = (blockIdx.x * blockDim.x + threadIdx.x) >> 5;
    int lane = threadIdx.x & 31;
    int q = lane >> 3;
    int hl = lane & 7;
    int node = warp * 4 + q;
    if (node >= N) return;
    int beg = g_rowptr[node], end = g_rowptr[node + 1];
    int ch = hl * 4;
    float adv = g_ad2[node];

    float s = 0.f;
    float a0 = 0.f, a1 = 0.f, a2 = 0.f, a3 = 0.f;
    for (int p = beg; p < end; ++p) {
        int src = g_csrsrc[p];
        float e = __ldg(&g_as2[src]) + adv;
        float4 h = *reinterpret_cast<const float4*>(&g_H2[src * 32 + ch]);
        float w = __expf(fmaxf(e, 0.2f * e));
        s += w;
        a0 = fmaf(w, h.x, a0);
        a1 = fmaf(w, h.y, a1);
        a2 = fmaf(w, h.z, a2);
        a3 = fmaf(w, h.w, a3);
    }
    float inv = 1.f / (s + 1e-16f);
    float4 bb = *reinterpret_cast<const float4*>(&b2[ch]);
    float4 o;
    o.x = fmaf(a0, inv, bb.x);
    o.y = fmaf(a1, inv, bb.y);
    o.z = fmaf(a2, inv, bb.z);
    o.w = fmaf(a3, inv, bb.w);
    *reinterpret_cast<float4*>(&out[node * 32 + ch]) = o;
}

// ---------------- launch: fork gemm1 ‖ CSR chain, join before agg1 ------------
extern "C" void kernel_launch(void* const* d_in, const int* in_sizes, int n_in,
                              void* d_out, int out_size) {
    const float* x      = (const float*)d_in[0];
    const int*   ei     = (const int*)  d_in[1];
    const float* W1     = (const float*)d_in[2];
    const float* a_src1 = (const float*)d_in[3];
    const float* a_dst1 = (const float*)d_in[4];
    const float* b1     = (const float*)d_in[5];
    const float* W2     = (const float*)d_in[6];
    const float* a_src2 = (const float*)d_in[7];
    const float* a_dst2 = (const float*)d_in[8];
    const float* b2     = (const float*)d_in[9];

    int N = in_sizes[0] / 128;
    int E = in_sizes[1] / 2;
    int nb = (N + 1023) / 1024;

    int gemmBlocks = (N + 127) / 128;
    int aggWarps = (N + 3) / 4;          // 4 nodes per warp

    // persistent aux stream + fork/join events (host-side objects; created once,
    // identical work every call — deterministic and graph-capturable)
    static cudaStream_t s2 = nullptr;
    static cudaEvent_t evFork = nullptr, evJoin = nullptr;
    if (s2 == nullptr) {
        cudaStreamCreateWithFlags(&s2, cudaStreamNonBlocking);
        cudaEventCreateWithFlags(&evFork, cudaEventDisableTiming);
        cudaEventCreateWithFlags(&evJoin, cudaEventDisableTiming);
    }

    // fork: GEMM1(+alphas1) on s2, independent of the CSR chain
    cudaEventRecord(evFork, 0);
    cudaStreamWaitEvent(s2, evFork, 0);
    k_gemm1<<<gemmBlocks, 256, 0, s2>>>(x, W1, a_src1, a_dst1, N);
    cudaEventRecord(evJoin, s2);

    // CSR chain on the main stream (non-spinning scan: interleaves with gemm1)
    k_hist<<<(E + 255) / 256, 256>>>(ei, E);
    k_scan_block<<<nb + 1, 1024>>>(W2, a_src2, a_dst2, N, nb);
    k_scan_add<<<nb, 1024>>>(N, nb);
    k_fill<<<(E + 255) / 256, 256>>>(ei, E);

    // join: agg1 needs H1/as1/ad1 (s2) + CSR (main)
    cudaStreamWaitEvent(0, evJoin, 0);
    k_agg1<<<(aggWarps * 32 + 255) / 256, 256>>>(b1, N);
    // layer 2
    k_gemm2<<<(N + 127) / 128, 128>>>(W2, N);
    k_agg2<<<(aggWarps * 32 + 255) / 256, 256>>>(b2, (float*)d_out, N);
}